// round 1
// baseline (speedup 1.0000x reference)
#include <cuda_runtime.h>
#include <cstdint>

// ---------------------------------------------------------------------------
// TensorizedEmbedding: vocab 32000 = 8*10*20*20, out 768 = 4*4*6*8,
// ranks (1,16,16,16,1).
//
// out[b, m0,m1,m2,m3] = sum_{r1,r2,r3} c0[0,d0,m0,r1] c1[r1,d1,m1,r2]
//                                      c2[r2,d2,m2,r3] c3[r3,d3,m3,0]
// with digits d0=idx/4000, d1=(idx/400)%10, d2=(idx/20)%20, d3=idx%20
// and flat output index j = (m0*4+m1)*48 + (m2*8+m3).
//
// Factorize around r2:
//   A [d0,d1][m0m1=16][r2=16]   (80 entries,  80 KB)
//   Bt[d2,d3][r2=16][m2m3=48]   (400 entries, 1.2 MB)
//   out_token[16x48] = A(d0,d1) @ Bt(d2,d3)      (12288 MACs / token)
// ---------------------------------------------------------------------------

__device__ __align__(16) float g_A[80 * 256];    //  80 KB scratch
__device__ __align__(16) float g_B[400 * 768];   // 1.2 MB scratch

// packed fp32x2 FMA (Blackwell): d = a*b + d  (two lanes at once)
__device__ __forceinline__ void ffma2(unsigned long long& d,
                                      unsigned long long a,
                                      unsigned long long b) {
    asm("fma.rn.f32x2 %0, %1, %2, %0;" : "+l"(d) : "l"(a), "l"(b));
}

// ---------------------------------------------------------------------------
// Precompute both partial-product tables. Blocks [0,80) build A, [80,480) Bt.
// ---------------------------------------------------------------------------
__global__ void __launch_bounds__(768) precompute_kernel(
    const float* __restrict__ c0, const float* __restrict__ c1,
    const float* __restrict__ c2, const float* __restrict__ c3)
{
    int blk = blockIdx.x;
    int t   = threadIdx.x;
    if (blk < 80) {
        if (t >= 256) return;
        int d0 = blk / 10, d1 = blk - d0 * 10;
        int m01 = t >> 4, r2 = t & 15;
        int m0 = m01 >> 2, m1 = m01 & 3;
        float s = 0.f;
        #pragma unroll
        for (int r1 = 0; r1 < 16; ++r1)
            s += c0[(d0 * 4 + m0) * 16 + r1] *
                 c1[((r1 * 10 + d1) * 4 + m1) * 16 + r2];
        g_A[blk * 256 + t] = s;          // layout [d0d1][m01][r2]
    } else {
        int p  = blk - 80;               // 0..399
        int d2 = p / 20, d3 = p - d2 * 20;
        int r2  = t / 48;
        int m23 = t - r2 * 48;
        int m2 = m23 >> 3, m3 = m23 & 7;
        float s = 0.f;
        #pragma unroll
        for (int r3 = 0; r3 < 16; ++r3)
            s += c2[((r2 * 20 + d2) * 6 + m2) * 16 + r3] *
                 c3[(r3 * 20 + d3) * 8 + m3];
        g_B[p * 768 + t] = s;            // layout [d2d3][r2][m23]
    }
}

// ---------------------------------------------------------------------------
// Main kernel: one warp per token. Lane (rg=l>>3, cg=l&7) owns a 4-row x
// 6-col tile of the 16x48 token output, computed as 3 packed f32x2 columns.
// A is staged duplicated (v,v) so the packed multiplicand is one LDS.64.
// Output staged in padded smem, then stored as coalesced STG.64.
// ---------------------------------------------------------------------------
#define TOK_PER_BLK 4

__global__ void __launch_bounds__(128) embed_kernel(
    const int* __restrict__ x, float* __restrict__ out, int nTok)
{
    __shared__ float2 sA2[TOK_PER_BLK][16 * 17];  // [m*17 + r], (v,v) pairs
    __shared__ float  sB [TOK_PER_BLK][768];      // [r*48 + m23]
    __shared__ float2 sO2[TOK_PER_BLK][16 * 25];  // [row*25 + col2] (padded)

    int w = threadIdx.x >> 5;
    int l = threadIdx.x & 31;
    int token = blockIdx.x * TOK_PER_BLK + w;
    if (token >= nTok) return;

    int idx = x[token];
    int d0 = idx / 4000; int rem = idx - d0 * 4000;
    int d1 = rem / 400;  rem -= d1 * 400;
    int d2 = rem / 20;   int d3 = rem - d2 * 20;

    const float4* Ap = (const float4*)(g_A + (d0 * 10 + d1) * 256);
    const float4* Bp = (const float4*)(g_B + (d2 * 20 + d3) * 768);

    // ---- stage A (duplicate each scalar into a float2) ----
    #pragma unroll
    for (int i = 0; i < 2; ++i) {
        float4 v = Ap[l + 32 * i];
        int e = 4 * (l + 32 * i);        // 4|e -> same m for all 4 elems
        int m = e >> 4, r = e & 15;
        float2* dst = &sA2[w][m * 17 + r];
        dst[0] = make_float2(v.x, v.x);
        dst[1] = make_float2(v.y, v.y);
        dst[2] = make_float2(v.z, v.z);
        dst[3] = make_float2(v.w, v.w);
    }
    // ---- stage Bt ----
    {
        float4* sB4 = (float4*)sB[w];
        #pragma unroll
        for (int i = 0; i < 6; ++i) sB4[l + 32 * i] = Bp[l + 32 * i];
    }
    __syncwarp();

    int rg = l >> 3;                     // row group: rows rg*4 .. rg*4+3
    int cg = l & 7;                      // col group: cols cg*6 .. cg*6+5

    const unsigned long long* aA =
        (const unsigned long long*)&sA2[w][0];
    const unsigned long long* bq =
        (const unsigned long long*)(sB[w] + cg * 6);   // ull idx: r*24 + p

    unsigned long long acc[4][3];
    #pragma unroll
    for (int i = 0; i < 4; ++i)
        #pragma unroll
        for (int p = 0; p < 3; ++p) acc[i][p] = 0ull;   // (0.0f, 0.0f)

    #pragma unroll
    for (int r = 0; r < 16; ++r) {
        unsigned long long a0 = aA[(rg * 4 + 0) * 17 + r];
        unsigned long long a1 = aA[(rg * 4 + 1) * 17 + r];
        unsigned long long a2 = aA[(rg * 4 + 2) * 17 + r];
        unsigned long long a3 = aA[(rg * 4 + 3) * 17 + r];
        unsigned long long b0 = bq[r * 24 + 0];
        unsigned long long b1 = bq[r * 24 + 1];
        unsigned long long b2 = bq[r * 24 + 2];
        ffma2(acc[0][0], a0, b0); ffma2(acc[0][1], a0, b1); ffma2(acc[0][2], a0, b2);
        ffma2(acc[1][0], a1, b0); ffma2(acc[1][1], a1, b1); ffma2(acc[1][2], a1, b2);
        ffma2(acc[2][0], a2, b0); ffma2(acc[2][1], a2, b1); ffma2(acc[2][2], a2, b2);
        ffma2(acc[3][0], a3, b0); ffma2(acc[3][1], a3, b1); ffma2(acc[3][2], a3, b2);
    }

    // ---- stage tile to padded smem (conflict-light STS.64) ----
    #pragma unroll
    for (int i = 0; i < 4; ++i) {
        int row = rg * 4 + i;
        unsigned long long* dst =
            (unsigned long long*)&sO2[w][row * 25 + cg * 3];
        dst[0] = acc[i][0];
        dst[1] = acc[i][1];
        dst[2] = acc[i][2];
    }
    __syncwarp();

    // ---- coalesced write-out: 384 float2 per token ----
    float2* outp = (float2*)out + (size_t)token * 384;
    const float2* so = &sO2[w][0];
    #pragma unroll
    for (int i = 0; i < 12; ++i) {
        int e = l + 32 * i;              // 0..383
        int row = e / 24;
        int c2  = e - row * 24;
        outp[e] = so[row * 25 + c2];
    }
}

// ---------------------------------------------------------------------------
extern "C" void kernel_launch(void* const* d_in, const int* in_sizes, int n_in,
                              void* d_out, int out_size) {
    const int*   x  = (const int*)  d_in[0];
    const float* c0 = (const float*)d_in[1];
    const float* c1 = (const float*)d_in[2];
    const float* c2 = (const float*)d_in[3];
    const float* c3 = (const float*)d_in[4];
    float* out = (float*)d_out;
    int nTok = in_sizes[0];              // 8*4096 = 32768

    precompute_kernel<<<480, 768>>>(c0, c1, c2, c3);

    int grid = (nTok + TOK_PER_BLK - 1) / TOK_PER_BLK;
    embed_kernel<<<grid, 128>>>(x, out, nTok);
}